// round 14
// baseline (speedup 1.0000x reference)
#include <cuda_runtime.h>
#include <cuda_fp16.h>
#include <math.h>
#include <stdint.h>

#define B_ 4
#define T_ 512
#define TAU_ 512
#define L_ 1024
#define DM_ 1024
#define H_ 16
#define D_ 64

// ---------------- scratch (device globals; no allocations allowed) ----------
__device__ __half g_xln[B_ * L_ * DM_];        //  8 MB  LN out (fp16)
__device__ __half g_qkv[B_ * L_ * 3 * DM_];    // 24 MB  [B,L,3072] fp16
__device__ __half g_phi[L_ * DM_];             //  2 MB
__device__ __half g_R[L_ * DM_];               //  2 MB
__device__ __half g_attn[B_ * T_ * DM_];       //  4 MB
__device__ __half g_wqkv[3 * DM_ * DM_];       //  6 MB  fp16 weights
__device__ __half g_wpos[DM_ * DM_];           //  2 MB
__device__ __half g_wout[DM_ * DM_];           //  2 MB

__device__ __forceinline__ uint32_t smem_u32(const void* p) {
    uint32_t a;
    asm("{ .reg .u64 t; cvta.to.shared.u64 t, %1; cvt.u32.u64 %0, t; }" : "=r"(a) : "l"(p));
    return a;
}
// fp16 mma, fp32 accum: m16n8k16
__device__ __forceinline__ void mma_f16(float& c0, float& c1, float& c2, float& c3,
                                        uint32_t a0, uint32_t a1, uint32_t a2, uint32_t a3,
                                        uint32_t b0, uint32_t b1) {
    asm volatile(
        "mma.sync.aligned.m16n8k16.row.col.f32.f16.f16.f32 "
        "{%0,%1,%2,%3},{%4,%5,%6,%7},{%8,%9},{%0,%1,%2,%3};"
        : "+f"(c0), "+f"(c1), "+f"(c2), "+f"(c3)
        : "r"(a0), "r"(a1), "r"(a2), "r"(a3), "r"(b0), "r"(b1));
}
// ldmatrix x4: 4 8x8 fp16 matrices (rows 0-7/8-15 x k-halves)
__device__ __forceinline__ void ldsm_x4(uint32_t& r0, uint32_t& r1, uint32_t& r2, uint32_t& r3,
                                        uint32_t addr) {
    asm volatile("ldmatrix.sync.aligned.m8n8.x4.shared.b16 {%0,%1,%2,%3}, [%4];"
                 : "=r"(r0), "=r"(r1), "=r"(r2), "=r"(r3) : "r"(addr));
}
__device__ __forceinline__ void cp16(uint32_t dst, const void* src) {
    asm volatile("cp.async.cg.shared.global [%0], [%1], 16;" :: "r"(dst), "l"(src));
}
__device__ __forceinline__ void cp_commit() {
    asm volatile("cp.async.commit_group;" ::: "memory");
}
__device__ __forceinline__ void cp_wait1() {
    asm volatile("cp.async.wait_group 1;" ::: "memory");
}

// ---------------- convert weights fp32 -> fp16 -------------------------------
__global__ __launch_bounds__(256) void round_h_kernel(const float* __restrict__ src,
                                                      __half* __restrict__ dst, int n4) {
    int i = blockIdx.x * blockDim.x + threadIdx.x;
    if (i < n4) {
        float4 v = ((const float4*)src)[i];
        ((__half2*)dst)[2 * i]     = __floats2half2_rn(v.x, v.y);
        ((__half2*)dst)[2 * i + 1] = __floats2half2_rn(v.z, v.w);
    }
}

// ---------------- LayerNorm over concat(memory, inputs), fp16 out ------------
__global__ __launch_bounds__(256) void ln_kernel(const float* __restrict__ inputs,
                          const float* __restrict__ memory,
                          const float* __restrict__ gamma,
                          const float* __restrict__ beta) {
    int row = blockIdx.x;
    int b = row >> 10, l = row & 1023;
    const float* src = (l < TAU_) ? memory + ((size_t)b * TAU_ + l) * DM_
                                  : inputs + ((size_t)b * T_ + (l - TAU_)) * DM_;
    int tid = threadIdx.x;
    float4 x = ((const float4*)src)[tid];
    float s  = x.x + x.y + x.z + x.w;
    float ss = x.x * x.x + x.y * x.y + x.z * x.z + x.w * x.w;
#pragma unroll
    for (int off = 16; off; off >>= 1) {
        s  += __shfl_xor_sync(0xffffffffu, s, off);
        ss += __shfl_xor_sync(0xffffffffu, ss, off);
    }
    __shared__ float red[16];
    int wid = tid >> 5, lane = tid & 31;
    if (lane == 0) { red[wid] = s; red[8 + wid] = ss; }
    __syncthreads();
    float ts = 0.f, tss = 0.f;
#pragma unroll
    for (int i = 0; i < 8; i++) { ts += red[i]; tss += red[8 + i]; }
    float mu   = ts * (1.0f / DM_);
    float var  = tss * (1.0f / DM_) - mu * mu;
    float rstd = rsqrtf(var + 1e-5f);
    float4 g  = ((const float4*)gamma)[tid];
    float4 bb = ((const float4*)beta)[tid];
    __half2* dst = (__half2*)(g_xln + (size_t)row * DM_);
    dst[2 * tid]     = __floats2half2_rn((x.x - mu) * rstd * g.x + bb.x,
                                         (x.y - mu) * rstd * g.y + bb.y);
    dst[2 * tid + 1] = __floats2half2_rn((x.z - mu) * rstd * g.z + bb.z,
                                         (x.w - mu) * rstd * g.w + bb.w);
}

// ---------------- positional features phi[l, :], fp16 out --------------------
__global__ __launch_bounds__(256) void phi_kernel() {
    int l = blockIdx.x;
    float pos = (float)(L_ - 1 - l);
    for (int f = threadIdx.x; f < 512; f += blockDim.x) {
        float ex  = (float)(2 * f) / 1024.0f;
        float inv = powf(10000.0f, -ex);
        float a = pos * inv;
        float sn, cs;
        sincosf(a, &sn, &cs);
        g_phi[(size_t)l * DM_ + f]       = __float2half_rn(sn);
        g_phi[(size_t)l * DM_ + 512 + f] = __float2half_rn(cs);
    }
}

// ---------------- cp.async 3-stage fp16 GEMM: C = A @ B^T --------------------
// 128x128x64 CTA K-chunk, 128 threads = 4 warps (2x2), warp tile 64x64.
// Fragments via ldmatrix.x4 (conflict-free with 36-word stride).
#define GST 36
#define STAGE_WORDS (128 * GST)
#define STAGE_BYTES (STAGE_WORDS * 4)
#define STAGES 3
#define GEMM_SMEM (STAGES * 2 * STAGE_WORDS * 4)   // 110592 B -> 2 CTAs/SM

#define GEMM_ISSUE(kcc, st) do {                                            \
    const __half* Ag = A  + (size_t)bm * K + (kcc) * 64;                    \
    const __half* Bg = Bm + (size_t)bn * K + (kcc) * 64;                    \
    uint32_t baseA = aAddr + (st) * STAGE_BYTES;                            \
    uint32_t baseB = bAddr + (st) * STAGE_BYTES;                            \
    _Pragma("unroll")                                                       \
    for (int p = 0; p < 8; p++) {                                           \
        int sgm = tid + 128 * p;                                            \
        int row = sgm >> 3, cs = sgm & 7;                                   \
        uint32_t off = (uint32_t)(row * GST + cs * 4) * 4;                  \
        cp16(baseA + off, Ag + (size_t)row * K + cs * 8);                   \
        cp16(baseB + off, Bg + (size_t)row * K + cs * 8);                   \
    }                                                                       \
} while (0)

template <bool HOUT>
__global__ __launch_bounds__(128, 2) void gemm_mma(const __half* __restrict__ A,
                                                   const __half* __restrict__ Bm,
                                                   void* __restrict__ Cv,
                                                   int M, int N, int K) {
    extern __shared__ uint32_t smem_u[];
    uint32_t* sA = smem_u;
    uint32_t* sB = smem_u + STAGES * STAGE_WORDS;
    uint32_t aAddr = smem_u32(sA);
    uint32_t bAddr = smem_u32(sB);

    int tid = threadIdx.x;
    int wid = tid >> 5, lane = tid & 31;
    int warp_m = wid >> 1, warp_n = wid & 1;
    int bm = blockIdx.y * 128, bn = blockIdx.x * 128;
    int qrow = lane >> 2, qcol = lane & 3;
    int lrow = lane & 15;              // ldmatrix row within 16-row block
    int lcol = (lane >> 4) * 4;        // ldmatrix k-half word offset

    float c[4][8][4];
#pragma unroll
    for (int mt = 0; mt < 4; mt++)
#pragma unroll
        for (int nt = 0; nt < 8; nt++)
#pragma unroll
            for (int e = 0; e < 4; e++) c[mt][nt][e] = 0.f;

    const int NC = K / 64;

    GEMM_ISSUE(0, 0); cp_commit();
    GEMM_ISSUE(1, 1); cp_commit();

    uint32_t aFragOff = (uint32_t)((warp_m * 64 + lrow) * GST + lcol) * 4;
    uint32_t bFragOff = (uint32_t)((warp_n * 64 + lrow) * GST + lcol) * 4;

    int st = 0;
    for (int kc = 0; kc < NC; kc++) {
        cp_wait1();
        __syncthreads();
        uint32_t aBase = aAddr + st * STAGE_BYTES + aFragOff;
        uint32_t bBase = bAddr + st * STAGE_BYTES + bFragOff;
#pragma unroll
        for (int ks = 0; ks < 4; ks++) {
            uint32_t kb = (uint32_t)(ks * 32);         // ks*8 words * 4B
            uint32_t af[4][4], bf[8][2];
#pragma unroll
            for (int mt = 0; mt < 4; mt++)
                ldsm_x4(af[mt][0], af[mt][1], af[mt][2], af[mt][3],
                        aBase + (uint32_t)(mt * 16 * GST * 4) + kb);
#pragma unroll
            for (int p = 0; p < 4; p++) {
                uint32_t r0, r1, r2, r3;
                ldsm_x4(r0, r1, r2, r3, bBase + (uint32_t)(p * 16 * GST * 4) + kb);
                bf[2 * p][0] = r0; bf[2 * p][1] = r2;
                bf[2 * p + 1][0] = r1; bf[2 * p + 1][1] = r3;
            }
#pragma unroll
            for (int nt = 0; nt < 8; nt++)
#pragma unroll
                for (int mt = 0; mt < 4; mt++)
                    mma_f16(c[mt][nt][0], c[mt][nt][1], c[mt][nt][2], c[mt][nt][3],
                            af[mt][0], af[mt][1], af[mt][2], af[mt][3],
                            bf[nt][0], bf[nt][1]);
        }
        int kn = kc + 2;
        if (kn < NC) {
            int sn = st + 2; if (sn >= STAGES) sn -= STAGES;
            GEMM_ISSUE(kn, sn);
        }
        cp_commit();
        __syncthreads();
        if (++st == STAGES) st = 0;
    }

#pragma unroll
    for (int mt = 0; mt < 4; mt++) {
        int row = bm + warp_m * 64 + mt * 16 + qrow;
#pragma unroll
        for (int nt = 0; nt < 8; nt++) {
            int col = bn + warp_n * 64 + nt * 8 + 2 * qcol;
            if (HOUT) {
                __half* Ch = (__half*)Cv;
                *(__half2*)(Ch + (size_t)row * N + col) =
                    __floats2half2_rn(c[mt][nt][0], c[mt][nt][1]);
                *(__half2*)(Ch + (size_t)(row + 8) * N + col) =
                    __floats2half2_rn(c[mt][nt][2], c[mt][nt][3]);
            } else {
                float* Cf = (float*)Cv;
                *(float2*)(Cf + (size_t)row * N + col) = make_float2(c[mt][nt][0], c[mt][nt][1]);
                *(float2*)(Cf + (size_t)(row + 8) * N + col) = make_float2(c[mt][nt][2], c[mt][nt][3]);
            }
        }
    }
}

// ---------------- fp16 mma fused relative flash attention --------------------
// 87KB smem -> 2 CTAs/SM. Shared buffer cycles R -> K -> V per tile.
// Fragments via ldmatrix.x4; vectorized 16B tile loads.
#define AWW 36      // word stride of fp16 tiles (64 halves + pad)
#define AWH 72      // half stride (144 B, 16B-aligned)
#define ASW 68      // fp32 score row stride
#define AEW 132     // fp32 E ring stride
#define ATT_SMEM ((4 * 64 * AWW + 64 * ASW + 64 * AEW + 192) * 4)

__global__ __launch_bounds__(256, 2) void attn_mma(const float* __restrict__ uvar,
                                                   const float* __restrict__ vvar) {
    extern __shared__ float sm[];
    __half* hQU = (__half*)sm;                         // [64][AWH]
    __half* hQV = hQU + 64 * AWH;                      // [64][AWH]
    __half* hBf = hQV + 64 * AWH;                      // [64][AWH] R->K->V
    __half* hP  = hBf + 64 * AWH;                      // [64][AWH] probs
    float* sS   = (float*)(hP + 64 * AWH);             // [64][ASW] scores
    float* sE   = sS + 64 * ASW;                       // [64][AEW] E ring
    float* sm_m = sE + 64 * AEW;
    float* sm_l = sm_m + 64;
    float* sm_c = sm_l + 64;

    int i0 = blockIdx.x * 64;
    int b  = blockIdx.y >> 4;
    int h  = blockIdx.y & 15;
    int tid = threadIdx.x;
    int wid = tid >> 5, lane = tid & 31;
    int wm = wid >> 1, wn = wid & 1;
    int qrow = lane >> 2, qcol = lane & 3;
    int lrow = lane & 15;
    int lcol = (lane >> 4) * 4;

    // ldmatrix base addresses (per-lane)
    uint32_t aOffA = (uint32_t)((wm * 16 + lrow) * AWW + lcol) * 4;   // A-side (m16)
    uint32_t adQU = smem_u32(hQU) + aOffA;
    uint32_t adQV = smem_u32(hQV) + aOffA;
    uint32_t adP  = smem_u32(hP)  + aOffA;
    uint32_t adBf = smem_u32(hBf) + (uint32_t)((wn * 32 + lrow) * AWW + lcol) * 4;

    // load q tiles (16B vectorized), add u/v in fp32, store fp16
#pragma unroll
    for (int p = 0; p < 2; p++) {
        int s = tid + 256 * p;            // 0..511
        int i = s >> 3, seg = s & 7;
        uint4 q4 = *(const uint4*)(g_qkv + ((size_t)(b * L_ + TAU_ + i0 + i)) * 3072 + h * 64 + seg * 8);
        const __half* qh = (const __half*)&q4;
        const float* up = uvar + h * 64 + seg * 8;
        const float* vp = vvar + h * 64 + seg * 8;
        __half2 ou[4], ov[4];
#pragma unroll
        for (int k = 0; k < 4; k++) {
            float q0 = __half2float(qh[2 * k]), q1 = __half2float(qh[2 * k + 1]);
            ou[k] = __floats2half2_rn(q0 + up[2 * k], q1 + up[2 * k + 1]);
            ov[k] = __floats2half2_rn(q0 + vp[2 * k], q1 + vp[2 * k + 1]);
        }
        *(uint4*)(hQU + i * AWH + seg * 8) = *(uint4*)ou;
        *(uint4*)(hQV + i * AWH + seg * 8) = *(uint4*)ov;
    }
    if (tid < 64) { sm_m[tid] = -INFINITY; sm_l[tid] = 0.f; }

    float o[4][4];
#pragma unroll
    for (int nt = 0; nt < 4; nt++)
#pragma unroll
        for (int e = 0; e < 4; e++) o[nt][e] = 0.f;

    int ntiles = (TAU_ + i0 + 63) / 64 + 1;
    int rnext = 448 - i0;

    for (int jt = 0; jt < ntiles; jt++) {
        int j0 = jt * 64;
        int rband = j0 + 448 - i0;
        __syncthreads();                  // prev PV done with hBf(V), hP

        // ---- Phase A: R batches -> E ring halves ----
        while (rnext < rband + 128) {
#pragma unroll
            for (int p = 0; p < 2; p++) {
                int s = tid + 256 * p;
                int r = s >> 3, seg = s & 7;
                int rr = rnext + r; rr = rr > (L_ - 1) ? (L_ - 1) : rr;
                *(uint4*)(hBf + r * AWH + seg * 8) =
                    *(const uint4*)(g_R + (size_t)rr * DM_ + h * 64 + seg * 8);
            }
            __syncthreads();
            int hf = (rnext >> 6) & 1;
            float ce[4][4];
#pragma unroll
            for (int nt = 0; nt < 4; nt++)
#pragma unroll
                for (int e = 0; e < 4; e++) ce[nt][e] = 0.f;
#pragma unroll
            for (int ks = 0; ks < 4; ks++) {
                uint32_t kb = (uint32_t)(ks * 32);
                uint32_t a0, a1, a2, a3;
                ldsm_x4(a0, a1, a2, a3, adQV + kb);
                uint32_t bf[4][2];
#pragma unroll
                for (int p = 0; p < 2; p++) {
                    uint32_t r0, r1, r2, r3;
                    ldsm_x4(r0, r1, r2, r3, adBf + (uint32_t)(p * 16 * AWW * 4) + kb);
                    bf[2 * p][0] = r0; bf[2 * p][1] = r2;
                    bf[2 * p + 1][0] = r1; bf[2 * p + 1][1] = r3;
                }
#pragma unroll
                for (int nt = 0; nt < 4; nt++)
                    mma_f16(ce[nt][0], ce[nt][1], ce[nt][2], ce[nt][3],
                            a0, a1, a2, a3, bf[nt][0], bf[nt][1]);
            }
            {
                int row = wm * 16 + qrow;
#pragma unroll
                for (int nt = 0; nt < 4; nt++) {
                    int col = hf * 64 + wn * 32 + nt * 8 + 2 * qcol;
                    sE[row * AEW + col]     = ce[nt][0];
                    sE[row * AEW + col + 1] = ce[nt][1];
                    sE[(row + 8) * AEW + col]     = ce[nt][2];
                    sE[(row + 8) * AEW + col + 1] = ce[nt][3];
                }
            }
            __syncthreads();
            rnext += 64;
        }

        // ---- Phase B: K tile (16B copies) -> S = QU @ K^T ----
#pragma unroll
        for (int p = 0; p < 2; p++) {
            int s = tid + 256 * p;
            int j = s >> 3, seg = s & 7;
            *(uint4*)(hBf + j * AWH + seg * 8) =
                *(const uint4*)(g_qkv + ((size_t)(b * L_ + j0 + j)) * 3072 + 1024 + h * 64 + seg * 8);
        }
        __syncthreads();
        {
            float cs[4][4];
#pragma unroll
            for (int nt = 0; nt < 4; nt++)
#pragma unroll
                for (int e = 0; e < 4; e++) cs[nt][e] = 0.f;
#pragma unroll
            for (int ks = 0; ks < 4; ks++) {
                uint32_t kb = (uint32_t)(ks * 32);
                uint32_t a0, a1, a2, a3;
                ldsm_x4(a0, a1, a2, a3, adQU + kb);
                uint32_t bf[4][2];
#pragma unroll
                for (int p = 0; p < 2; p++) {
                    uint32_t r0, r1, r2, r3;
                    ldsm_x4(r0, r1, r2, r3, adBf + (uint32_t)(p * 16 * AWW * 4) + kb);
                    bf[2 * p][0] = r0; bf[2 * p][1] = r2;
                    bf[2 * p + 1][0] = r1; bf[2 * p + 1][1] = r3;
                }
#pragma unroll
                for (int nt = 0; nt < 4; nt++)
                    mma_f16(cs[nt][0], cs[nt][1], cs[nt][2], cs[nt][3],
                            a0, a1, a2, a3, bf[nt][0], bf[nt][1]);
            }
            int row = wm * 16 + qrow;
#pragma unroll
            for (int nt = 0; nt < 4; nt++) {
                int col = wn * 32 + nt * 8 + 2 * qcol;
                sS[row * ASW + col]     = cs[nt][0];
                sS[row * ASW + col + 1] = cs[nt][1];
                sS[(row + 8) * ASW + col]     = cs[nt][2];
                sS[(row + 8) * ASW + col + 1] = cs[nt][3];
            }
        }
        __syncthreads();                  // S ready; hBf(K) consumed

        // ---- Phase C: softmax (S -> hP) + V load into hBf ----
        {
            int row = tid >> 2, cbase = (tid & 3) * 16;
            int gi = i0 + row;
            float oldm = sm_m[row];
            int sb = rband + 63 - row;
            float s16[16], mx = -INFINITY;
#pragma unroll
            for (int x = 0; x < 16; x++) {
                int jp = cbase + x;
                float s = (sS[row * ASW + jp] + sE[row * AEW + ((sb + jp) & 127)]) * 0.125f;
                if (j0 + jp > TAU_ + gi) s = -1e30f;
                s16[x] = s;
                mx = fmaxf(mx, s);
            }
            mx = fmaxf(mx, __shfl_xor_sync(0xffffffffu, mx, 1));
            mx = fmaxf(mx, __shfl_xor_sync(0xffffffffu, mx, 2));
            float mnew = fmaxf(oldm, mx);
            float corr = __expf(oldm - mnew);
            float ps = 0.f;
#pragma unroll
            for (int x = 0; x < 16; x += 2) {
                float p0 = __expf(s16[x] - mnew);
                float p1 = __expf(s16[x + 1] - mnew);
                *(__half2*)(hP + row * AWH + cbase + x) = __floats2half2_rn(p0, p1);
                ps += p0 + p1;
            }
            ps += __shfl_xor_sync(0xffffffffu, ps, 1);
            ps += __shfl_xor_sync(0xffffffffu, ps, 2);
            if ((tid & 3) == 0) {
                sm_m[row] = mnew;
                sm_l[row] = sm_l[row] * corr + ps;
                sm_c[row] = corr;
            }
        }
        // V tile (transpose to d-major): vectorized LDG, half-merged STS
#pragma unroll
        for (int p = 0; p < 2; p++) {
            int s = tid + 256 * p;
            int j = s & 63, dg = s >> 6;   // consecutive lanes -> consecutive j
            uint4 v4 = *(const uint4*)(g_qkv + ((size_t)(b * L_ + j0 + j)) * 3072 + 2048 + h * 64 + dg * 8);
            const __half* vh = (const __half*)&v4;
#pragma unroll
            for (int k = 0; k < 8; k++)
                hBf[(dg * 8 + k) * AWH + j] = vh[k];
        }
        __syncthreads();

        // ---- Phase D: O = O*corr + P @ V ----
        {
            float cr0 = sm_c[wm * 16 + qrow];
            float cr1 = sm_c[wm * 16 + qrow + 8];
#pragma unroll
            for (int nt = 0; nt < 4; nt++) {
                o[nt][0] *= cr0; o[nt][1] *= cr0;
                o[nt][2] *= cr1; o[nt][3] *= cr1;
            }
#pragma unroll
            for (int ks = 0; ks < 4; ks++) {
                uint32_t kb = (uint32_t)(ks * 32);
                uint32_t a0, a1, a2, a3;
                ldsm_x4(a0, a1, a2, a3, adP + kb);
                uint32_t bf[4][2];
#pragma unroll
                for (int p = 0; p < 2; p++) {
                    uint32_t r0, r1, r2, r3;
                    ldsm_x4(r0, r1, r2, r3, adBf + (uint32_t)(p * 16 * AWW * 4) + kb);
                    bf[2 * p][0] = r0; bf[2 * p][1] = r2;
                    bf[2 * p + 1][0] = r1; bf[2 * p + 1][1] = r3;
                }
#pragma unroll
                for (int nt = 0; nt < 4; nt++)
                    mma_f16(o[nt][0], o[nt][1], o[nt][2], o[nt][3],
                            a0, a1, a2, a3, bf[nt][0], bf[nt][1]);
            }
        }
    }

    // write O fp16 (consumed by out-proj GEMM)
    {
        int row = wm * 16 + qrow;
        float inv0 = 1.0f / sm_l[row];
        float inv1 = 1.0f / sm_l[row + 8];
#pragma unroll
        for (int nt = 0; nt < 4; nt++) {
            int col = h * 64 + wn * 32 + nt * 8 + 2 * qcol;
            *(__half2*)(g_attn + ((size_t)(b * T_ + i0 + row)) * DM_ + col) =
                __floats2half2_rn(o[nt][0] * inv0, o[nt][1] * inv0);
            *(__half2*)(g_attn + ((size_t)(b * T_ + i0 + row + 8)) * DM_ + col) =
                __floats2half2_rn(o[nt][2] * inv1, o[nt][3] * inv1);
        }
    }
}

// ---------------- host launcher ---------------------------------------------
extern "C" void kernel_launch(void* const* d_in, const int* in_sizes, int n_in,
                              void* d_out, int out_size) {
    const float* inputs = (const float*)d_in[0];
    const float* memory = (const float*)d_in[1];
    const float* w_qkv  = (const float*)d_in[2];
    const float* w_pos  = (const float*)d_in[3];
    const float* w_out  = (const float*)d_in[4];
    const float* uvar   = (const float*)d_in[5];
    const float* vvar   = (const float*)d_in[6];
    const float* gamma  = (const float*)d_in[7];
    const float* beta   = (const float*)d_in[8];
    float* out = (float*)d_out;

    __half *xln, *qkv, *phi, *R, *attn, *wqkv, *wpos, *wout;
    cudaGetSymbolAddress((void**)&xln,  g_xln);
    cudaGetSymbolAddress((void**)&qkv,  g_qkv);
    cudaGetSymbolAddress((void**)&phi,  g_phi);
    cudaGetSymbolAddress((void**)&R,    g_R);
    cudaGetSymbolAddress((void**)&attn, g_attn);
    cudaGetSymbolAddress((void**)&wqkv, g_wqkv);
    cudaGetSymbolAddress((void**)&wpos, g_wpos);
    cudaGetSymbolAddress((void**)&wout, g_wout);

    cudaFuncSetAttribute(attn_mma,
                         cudaFuncAttributeMaxDynamicSharedMemorySize, ATT_SMEM);
    cudaFuncSetAttribute(gemm_mma<true>,
                         cudaFuncAttributeMaxDynamicSharedMemorySize, GEMM_SMEM);
    cudaFuncSetAttribute(gemm_mma<false>,
                         cudaFuncAttributeMaxDynamicSharedMemorySize, GEMM_SMEM);

    // order keeps ncu capture slot (#4) on the QKV GEMM
    // 1) LayerNorm + concat (fp16 out)
    ln_kernel<<<B_ * L_, 256>>>(inputs, memory, gamma, beta);
    // 2) positional features (fp16 out)
    phi_kernel<<<L_, 256>>>();
    // 3) w_qkv -> fp16
    round_h_kernel<<<(3 * DM_ * DM_ / 4 + 255) / 256, 256>>>(w_qkv, wqkv, 3 * DM_ * DM_ / 4);
    // 4) QKV = xln @ w_qkv^T   [4096 x 3072 x 1024]
    gemm_mma<true><<<dim3(3072 / 128, (B_ * L_) / 128), 128, GEMM_SMEM>>>(
        xln, wqkv, qkv, B_ * L_, 3 * DM_, DM_);
    // 5) w_pos -> fp16
    round_h_kernel<<<(DM_ * DM_ / 4 + 255) / 256, 256>>>(w_pos, wpos, DM_ * DM_ / 4);
    // 6) R = phi @ w_pos^T     [1024 x 1024 x 1024]
    gemm_mma<true><<<dim3(DM_ / 128, L_ / 128), 128, GEMM_SMEM>>>(
        phi, wpos, R, L_, DM_, DM_);
    // 7) fused relative attention (fp16 tensor-core)
    attn_mma<<<dim3(T_ / 64, B_ * H_), 256, ATT_SMEM>>>(uvar, vvar);
    // 8) w_out -> fp16
    round_h_kernel<<<(DM_ * DM_ / 4 + 255) / 256, 256>>>(w_out, wout, DM_ * DM_ / 4);
    // 9) out = attn @ w_out^T  [2048 x 1024 x 1024]  (fp32 out)
    gemm_mma<false><<<dim3(DM_ / 128, (B_ * T_) / 128), 128, GEMM_SMEM>>>(
        attn, wout, out, B_ * T_, DM_, DM_);
}

// round 16
// speedup vs baseline: 1.0750x; 1.0750x over previous
#include <cuda_runtime.h>
#include <cuda_fp16.h>
#include <math.h>
#include <stdint.h>

#define B_ 4
#define T_ 512
#define TAU_ 512
#define L_ 1024
#define DM_ 1024
#define H_ 16
#define D_ 64

// ---------------- scratch (device globals; no allocations allowed) ----------
__device__ __half g_xln[B_ * L_ * DM_];        //  8 MB  LN out (fp16)
__device__ __half g_qkv[B_ * L_ * 3 * DM_];    // 24 MB  [B,L,3072] fp16
__device__ __half g_phi[L_ * DM_];             //  2 MB
__device__ __half g_R[L_ * DM_];               //  2 MB
__device__ __half g_attn[B_ * T_ * DM_];       //  4 MB
__device__ __half g_wqkv[3 * DM_ * DM_];       //  6 MB  fp16 weights
__device__ __half g_wpos[DM_ * DM_];           //  2 MB
__device__ __half g_wout[DM_ * DM_];           //  2 MB

__device__ __forceinline__ uint32_t smem_u32(const void* p) {
    uint32_t a;
    asm("{ .reg .u64 t; cvta.to.shared.u64 t, %1; cvt.u32.u64 %0, t; }" : "=r"(a) : "l"(p));
    return a;
}
// fp16 mma, fp32 accum: m16n8k16
__device__ __forceinline__ void mma_f16(float& c0, float& c1, float& c2, float& c3,
                                        uint32_t a0, uint32_t a1, uint32_t a2, uint32_t a3,
                                        uint32_t b0, uint32_t b1) {
    asm volatile(
        "mma.sync.aligned.m16n8k16.row.col.f32.f16.f16.f32 "
        "{%0,%1,%2,%3},{%4,%5,%6,%7},{%8,%9},{%0,%1,%2,%3};"
        : "+f"(c0), "+f"(c1), "+f"(c2), "+f"(c3)
        : "r"(a0), "r"(a1), "r"(a2), "r"(a3), "r"(b0), "r"(b1));
}
__device__ __forceinline__ void cp16(uint32_t dst, const void* src) {
    asm volatile("cp.async.cg.shared.global [%0], [%1], 16;" :: "r"(dst), "l"(src));
}
__device__ __forceinline__ void cp_commit() {
    asm volatile("cp.async.commit_group;" ::: "memory");
}
__device__ __forceinline__ void cp_wait1() {
    asm volatile("cp.async.wait_group 1;" ::: "memory");
}

// ---------------- convert weights fp32 -> fp16 -------------------------------
__global__ __launch_bounds__(256) void round_h_kernel(const float* __restrict__ src,
                                                      __half* __restrict__ dst, int n4) {
    int i = blockIdx.x * blockDim.x + threadIdx.x;
    if (i < n4) {
        float4 v = ((const float4*)src)[i];
        ((__half2*)dst)[2 * i]     = __floats2half2_rn(v.x, v.y);
        ((__half2*)dst)[2 * i + 1] = __floats2half2_rn(v.z, v.w);
    }
}

// ---------------- LayerNorm over concat(memory, inputs), fp16 out ------------
__global__ __launch_bounds__(256) void ln_kernel(const float* __restrict__ inputs,
                          const float* __restrict__ memory,
                          const float* __restrict__ gamma,
                          const float* __restrict__ beta) {
    int row = blockIdx.x;
    int b = row >> 10, l = row & 1023;
    const float* src = (l < TAU_) ? memory + ((size_t)b * TAU_ + l) * DM_
                                  : inputs + ((size_t)b * T_ + (l - TAU_)) * DM_;
    int tid = threadIdx.x;
    float4 x = ((const float4*)src)[tid];
    float s  = x.x + x.y + x.z + x.w;
    float ss = x.x * x.x + x.y * x.y + x.z * x.z + x.w * x.w;
#pragma unroll
    for (int off = 16; off; off >>= 1) {
        s  += __shfl_xor_sync(0xffffffffu, s, off);
        ss += __shfl_xor_sync(0xffffffffu, ss, off);
    }
    __shared__ float red[16];
    int wid = tid >> 5, lane = tid & 31;
    if (lane == 0) { red[wid] = s; red[8 + wid] = ss; }
    __syncthreads();
    float ts = 0.f, tss = 0.f;
#pragma unroll
    for (int i = 0; i < 8; i++) { ts += red[i]; tss += red[8 + i]; }
    float mu   = ts * (1.0f / DM_);
    float var  = tss * (1.0f / DM_) - mu * mu;
    float rstd = rsqrtf(var + 1e-5f);
    float4 g  = ((const float4*)gamma)[tid];
    float4 bb = ((const float4*)beta)[tid];
    __half2* dst = (__half2*)(g_xln + (size_t)row * DM_);
    dst[2 * tid]     = __floats2half2_rn((x.x - mu) * rstd * g.x + bb.x,
                                         (x.y - mu) * rstd * g.y + bb.y);
    dst[2 * tid + 1] = __floats2half2_rn((x.z - mu) * rstd * g.z + bb.z,
                                         (x.w - mu) * rstd * g.w + bb.w);
}

// ---------------- positional features phi[l, :], fp16 out --------------------
__global__ __launch_bounds__(256) void phi_kernel() {
    int l = blockIdx.x;
    float pos = (float)(L_ - 1 - l);
    for (int f = threadIdx.x; f < 512; f += blockDim.x) {
        float ex  = (float)(2 * f) / 1024.0f;
        float inv = powf(10000.0f, -ex);
        float a = pos * inv;
        float sn, cs;
        sincosf(a, &sn, &cs);
        g_phi[(size_t)l * DM_ + f]       = __float2half_rn(sn);
        g_phi[(size_t)l * DM_ + 512 + f] = __float2half_rn(cs);
    }
}

// ---------------- cp.async 3-stage fp16 GEMM: C = A @ B^T --------------------
// 128x128x64 CTA K-chunk, 256 threads = 8 warps (2m x 4n), warp tile 64x32.
// Scalar LDS fragment loads (measured faster than ldmatrix in R14).
#define GST 36
#define STAGE_WORDS (128 * GST)
#define STAGE_BYTES (STAGE_WORDS * 4)
#define STAGES 3
#define GEMM_SMEM (STAGES * 2 * STAGE_WORDS * 4)   // 110592 B -> 2 CTAs/SM

#define GEMM_ISSUE(kcc, st) do {                                            \
    const __half* Ag = A  + (size_t)bm * K + (kcc) * 64;                    \
    const __half* Bg = Bm + (size_t)bn * K + (kcc) * 64;                    \
    uint32_t baseA = aAddr + (st) * STAGE_BYTES;                            \
    uint32_t baseB = bAddr + (st) * STAGE_BYTES;                            \
    _Pragma("unroll")                                                       \
    for (int p = 0; p < 4; p++) {                                           \
        int sgm = tid + 256 * p;                                            \
        int row = sgm >> 3, cs = sgm & 7;                                   \
        uint32_t off = (uint32_t)(row * GST + cs * 4) * 4;                  \
        cp16(baseA + off, Ag + (size_t)row * K + cs * 8);                   \
        cp16(baseB + off, Bg + (size_t)row * K + cs * 8);                   \
    }                                                                       \
} while (0)

template <bool HOUT>
__global__ __launch_bounds__(256, 2) void gemm_mma(const __half* __restrict__ A,
                                                   const __half* __restrict__ Bm,
                                                   void* __restrict__ Cv,
                                                   int M, int N, int K) {
    extern __shared__ uint32_t smem_u[];
    uint32_t* sA = smem_u;
    uint32_t* sB = smem_u + STAGES * STAGE_WORDS;
    uint32_t aAddr = smem_u32(sA);
    uint32_t bAddr = smem_u32(sB);

    int tid = threadIdx.x;
    int wid = tid >> 5, lane = tid & 31;
    int warp_m = wid >> 2, warp_n = wid & 3;    // 2m x 4n
    int bm = blockIdx.y * 128, bn = blockIdx.x * 128;
    int qrow = lane >> 2, qcol = lane & 3;

    float c[4][4][4];
#pragma unroll
    for (int mt = 0; mt < 4; mt++)
#pragma unroll
        for (int nt = 0; nt < 4; nt++)
#pragma unroll
            for (int e = 0; e < 4; e++) c[mt][nt][e] = 0.f;

    const int NC = K / 64;

    GEMM_ISSUE(0, 0); cp_commit();
    GEMM_ISSUE(1, 1); cp_commit();

    int st = 0;
    for (int kc = 0; kc < NC; kc++) {
        cp_wait1();
        __syncthreads();
        const uint32_t* cA = sA + st * STAGE_WORDS;
        const uint32_t* cB = sB + st * STAGE_WORDS;
#pragma unroll
        for (int ks = 0; ks < 4; ks++) {
            int kk = ks * 8;
            uint32_t af[4][4], bf[4][2];
#pragma unroll
            for (int mt = 0; mt < 4; mt++) {
                int r = warp_m * 64 + mt * 16 + qrow;
                af[mt][0] = cA[r * GST + kk + qcol];
                af[mt][1] = cA[(r + 8) * GST + kk + qcol];
                af[mt][2] = cA[r * GST + kk + qcol + 4];
                af[mt][3] = cA[(r + 8) * GST + kk + qcol + 4];
            }
#pragma unroll
            for (int nt = 0; nt < 4; nt++) {
                int rn = warp_n * 32 + nt * 8 + qrow;
                bf[nt][0] = cB[rn * GST + kk + qcol];
                bf[nt][1] = cB[rn * GST + kk + qcol + 4];
            }
#pragma unroll
            for (int mt = 0; mt < 4; mt++)
#pragma unroll
                for (int nt = 0; nt < 4; nt++)
                    mma_f16(c[mt][nt][0], c[mt][nt][1], c[mt][nt][2], c[mt][nt][3],
                            af[mt][0], af[mt][1], af[mt][2], af[mt][3],
                            bf[nt][0], bf[nt][1]);
        }
        int kn = kc + 2;
        if (kn < NC) {
            int sn = st + 2; if (sn >= STAGES) sn -= STAGES;
            GEMM_ISSUE(kn, sn);
        }
        cp_commit();
        __syncthreads();
        if (++st == STAGES) st = 0;
    }

#pragma unroll
    for (int mt = 0; mt < 4; mt++) {
        int row = bm + warp_m * 64 + mt * 16 + qrow;
#pragma unroll
        for (int nt = 0; nt < 4; nt++) {
            int col = bn + warp_n * 32 + nt * 8 + 2 * qcol;
            if (HOUT) {
                __half* Ch = (__half*)Cv;
                *(__half2*)(Ch + (size_t)row * N + col) =
                    __floats2half2_rn(c[mt][nt][0], c[mt][nt][1]);
                *(__half2*)(Ch + (size_t)(row + 8) * N + col) =
                    __floats2half2_rn(c[mt][nt][2], c[mt][nt][3]);
            } else {
                float* Cf = (float*)Cv;
                *(float2*)(Cf + (size_t)row * N + col) = make_float2(c[mt][nt][0], c[mt][nt][1]);
                *(float2*)(Cf + (size_t)(row + 8) * N + col) = make_float2(c[mt][nt][2], c[mt][nt][3]);
            }
        }
    }
}

// ---------------- fp16 mma fused relative flash attention (R11 version) ------
#define AWW 36      // word stride of fp16 tiles (64 halves + pad)
#define AWH 72      // half stride (144 B, 16B-aligned)
#define ASW 68      // fp32 score row stride
#define AEW 132     // fp32 E ring stride
#define ATT_SMEM ((4 * 64 * AWW + 64 * ASW + 64 * AEW + 192) * 4)

__global__ __launch_bounds__(256, 2) void attn_mma(const float* __restrict__ uvar,
                                                   const float* __restrict__ vvar) {
    extern __shared__ float sm[];
    __half* hQU = (__half*)sm;                         // [64][AWH]
    __half* hQV = hQU + 64 * AWH;                      // [64][AWH]
    __half* hBf = hQV + 64 * AWH;                      // [64][AWH] R->K->V
    __half* hP  = hBf + 64 * AWH;                      // [64][AWH] probs
    float* sS   = (float*)(hP + 64 * AWH);             // [64][ASW] scores
    float* sE   = sS + 64 * ASW;                       // [64][AEW] E ring
    float* sm_m = sE + 64 * AEW;
    float* sm_l = sm_m + 64;
    float* sm_c = sm_l + 64;

    const uint32_t* uQU = (const uint32_t*)hQU;
    const uint32_t* uQV = (const uint32_t*)hQV;
    const uint32_t* uBf = (const uint32_t*)hBf;
    const uint32_t* uP  = (const uint32_t*)hP;

    int i0 = blockIdx.x * 64;
    int b  = blockIdx.y >> 4;
    int h  = blockIdx.y & 15;
    int tid = threadIdx.x;
    int wid = tid >> 5, lane = tid & 31;
    int wm = wid >> 1, wn = wid & 1;
    int qrow = lane >> 2, qcol = lane & 3;

    // load q tiles (16B vectorized), add u/v in fp32, store fp16
#pragma unroll
    for (int p = 0; p < 2; p++) {
        int s = tid + 256 * p;            // 0..511
        int i = s >> 3, seg = s & 7;
        uint4 q4 = *(const uint4*)(g_qkv + ((size_t)(b * L_ + TAU_ + i0 + i)) * 3072 + h * 64 + seg * 8);
        const __half* qh = (const __half*)&q4;
        const float* up = uvar + h * 64 + seg * 8;
        const float* vp = vvar + h * 64 + seg * 8;
        __half2 ou[4], ov[4];
#pragma unroll
        for (int k = 0; k < 4; k++) {
            float q0 = __half2float(qh[2 * k]), q1 = __half2float(qh[2 * k + 1]);
            ou[k] = __floats2half2_rn(q0 + up[2 * k], q1 + up[2 * k + 1]);
            ov[k] = __floats2half2_rn(q0 + vp[2 * k], q1 + vp[2 * k + 1]);
        }
        *(uint4*)(hQU + i * AWH + seg * 8) = *(uint4*)ou;
        *(uint4*)(hQV + i * AWH + seg * 8) = *(uint4*)ov;
    }
    if (tid < 64) { sm_m[tid] = -INFINITY; sm_l[tid] = 0.f; }

    float o[4][4];
#pragma unroll
    for (int nt = 0; nt < 4; nt++)
#pragma unroll
        for (int e = 0; e < 4; e++) o[nt][e] = 0.f;

    int ntiles = (TAU_ + i0 + 63) / 64 + 1;
    int rnext = 448 - i0;

    for (int jt = 0; jt < ntiles; jt++) {
        int j0 = jt * 64;
        int rband = j0 + 448 - i0;
        __syncthreads();                  // prev PV done with hBf(V), hP

        // ---- Phase A: R batches -> E ring halves ----
        while (rnext < rband + 128) {
#pragma unroll
            for (int p = 0; p < 2; p++) {
                int s = tid + 256 * p;
                int r = s >> 3, seg = s & 7;
                int rr = rnext + r; rr = rr > (L_ - 1) ? (L_ - 1) : rr;
                *(uint4*)(hBf + r * AWH + seg * 8) =
                    *(const uint4*)(g_R + (size_t)rr * DM_ + h * 64 + seg * 8);
            }
            __syncthreads();
            int hf = (rnext >> 6) & 1;
            float ce[4][4];
#pragma unroll
            for (int nt = 0; nt < 4; nt++)
#pragma unroll
                for (int e = 0; e < 4; e++) ce[nt][e] = 0.f;
#pragma unroll
            for (int ks = 0; ks < 4; ks++) {
                int kk = ks * 8;
                int r = wm * 16 + qrow;
                uint32_t a0 = uQV[r * AWW + kk + qcol];
                uint32_t a1 = uQV[(r + 8) * AWW + kk + qcol];
                uint32_t a2 = uQV[r * AWW + kk + qcol + 4];
                uint32_t a3 = uQV[(r + 8) * AWW + kk + qcol + 4];
#pragma unroll
                for (int nt = 0; nt < 4; nt++) {
                    int rn = wn * 32 + nt * 8 + qrow;
                    uint32_t b0 = uBf[rn * AWW + kk + qcol];
                    uint32_t b1 = uBf[rn * AWW + kk + qcol + 4];
                    mma_f16(ce[nt][0], ce[nt][1], ce[nt][2], ce[nt][3],
                            a0, a1, a2, a3, b0, b1);
                }
            }
            {
                int row = wm * 16 + qrow;
#pragma unroll
                for (int nt = 0; nt < 4; nt++) {
                    int col = hf * 64 + wn * 32 + nt * 8 + 2 * qcol;
                    sE[row * AEW + col]     = ce[nt][0];
                    sE[row * AEW + col + 1] = ce[nt][1];
                    sE[(row + 8) * AEW + col]     = ce[nt][2];
                    sE[(row + 8) * AEW + col + 1] = ce[nt][3];
                }
            }
            __syncthreads();
            rnext += 64;
        }

        // ---- Phase B: K tile (16B copies) -> S = QU @ K^T ----
#pragma unroll
        for (int p = 0; p < 2; p++) {
            int s = tid + 256 * p;
            int j = s >> 3, seg = s & 7;
            *(uint4*)(hBf + j * AWH + seg * 8) =
                *(const uint4*)(g_qkv + ((size_t)(b * L_ + j0 + j)) * 3072 + 1024 + h * 64 + seg * 8);
        }
        __syncthreads();
        {
            float cs[4][4];
#pragma unroll
            for (int nt = 0; nt < 4; nt++)
#pragma unroll
                for (int e = 0; e < 4; e++) cs[nt][e] = 0.f;
#pragma unroll
            for (int ks = 0; ks < 4; ks++) {
                int kk = ks * 8;
                int r = wm * 16 + qrow;
                uint32_t a0 = uQU[r * AWW + kk + qcol];
                uint32_t a1 = uQU[(r + 8) * AWW + kk + qcol];
                uint32_t a2 = uQU[r * AWW + kk + qcol + 4];
                uint32_t a3 = uQU[(r + 8) * AWW + kk + qcol + 4];
#pragma unroll
                for (int nt = 0; nt < 4; nt++) {
                    int rn = wn * 32 + nt * 8 + qrow;
                    uint32_t b0 = uBf[rn * AWW + kk + qcol];
                    uint32_t b1 = uBf[rn * AWW + kk + qcol + 4];
                    mma_f16(cs[nt][0], cs[nt][1], cs[nt][2], cs[nt][3],
                            a0, a1, a2, a3, b0, b1);
                }
            }
            int row = wm * 16 + qrow;
#pragma unroll
            for (int nt = 0; nt < 4; nt++) {
                int col = wn * 32 + nt * 8 + 2 * qcol;
                sS[row * ASW + col]     = cs[nt][0];
                sS[row * ASW + col + 1] = cs[nt][1];
                sS[(row + 8) * ASW + col]     = cs[nt][2];
                sS[(row + 8) * ASW + col + 1] = cs[nt][3];
            }
        }
        __syncthreads();                  // S ready; hBf(K) consumed

        // ---- Phase C: softmax (S -> hP) + V load into hBf ----
        {
            int row = tid >> 2, cbase = (tid & 3) * 16;
            int gi = i0 + row;
            float oldm = sm_m[row];
            int sb = rband + 63 - row;
            float s16[16], mx = -INFINITY;
#pragma unroll
            for (int x = 0; x < 16; x++) {
                int jp = cbase + x;
                float s = (sS[row * ASW + jp] + sE[row * AEW + ((sb + jp) & 127)]) * 0.125f;
                if (j0 + jp > TAU_ + gi) s = -1e30f;
                s16[x] = s;
                mx = fmaxf(mx, s);
            }
            mx = fmaxf(mx, __shfl_xor_sync(0xffffffffu, mx, 1));
            mx = fmaxf(mx, __shfl_xor_sync(0xffffffffu, mx, 2));
            float mnew = fmaxf(oldm, mx);
            float corr = __expf(oldm - mnew);
            float ps = 0.f;
#pragma unroll
            for (int x = 0; x < 16; x += 2) {
                float p0 = __expf(s16[x] - mnew);
                float p1 = __expf(s16[x + 1] - mnew);
                *(__half2*)(hP + row * AWH + cbase + x) = __floats2half2_rn(p0, p1);
                ps += p0 + p1;
            }
            ps += __shfl_xor_sync(0xffffffffu, ps, 1);
            ps += __shfl_xor_sync(0xffffffffu, ps, 2);
            if ((tid & 3) == 0) {
                sm_m[row] = mnew;
                sm_l[row] = sm_l[row] * corr + ps;
                sm_c[row] = corr;
            }
        }
        // V tile (transpose to d-major): vectorized LDG, half-merged STS
#pragma unroll
        for (int p = 0; p < 2; p++) {
            int s = tid + 256 * p;
            int j = s & 63, dg = s >> 6;   // consecutive lanes -> consecutive j
            uint4 v4 = *(const uint4*)(g_qkv + ((size_t)(b * L_ + j0 + j)) * 3072 + 2048 + h * 64 + dg * 8);
            const __half* vh = (const __half*)&v4;
#pragma unroll
            for (int k = 0; k < 8; k++)
                hBf[(dg * 8 + k) * AWH + j] = vh[k];
        }
        __syncthreads();

        // ---- Phase D: O = O*corr + P @ V ----
        {
            float cr0 = sm_c[wm * 16 + qrow];
            float cr1 = sm_c[wm * 16 + qrow + 8];
#pragma unroll
            for (int nt = 0; nt < 4; nt++) {
                o[nt][0] *= cr0; o[nt][1] *= cr0;
                o[nt][2] *= cr1; o[nt][3] *= cr1;
            }
#pragma unroll
            for (int ks = 0; ks < 4; ks++) {
                int kk = ks * 8;
                int r = wm * 16 + qrow;
                uint32_t a0 = uP[r * AWW + kk + qcol];
                uint32_t a1 = uP[(r + 8) * AWW + kk + qcol];
                uint32_t a2 = uP[r * AWW + kk + qcol + 4];
                uint32_t a3 = uP[(r + 8) * AWW + kk + qcol + 4];
#pragma unroll
                for (int nt = 0; nt < 4; nt++) {
                    int rn = wn * 32 + nt * 8 + qrow;
                    uint32_t b0 = uBf[rn * AWW + kk + qcol];
                    uint32_t b1 = uBf[rn * AWW + kk + qcol + 4];
                    mma_f16(o[nt][0], o[nt][1], o[nt][2], o[nt][3],
                            a0, a1, a2, a3, b0, b1);
                }
            }
        }
    }

    // write O fp16 (consumed by out-proj GEMM)
    {
        int row = wm * 16 + qrow;
        float inv0 = 1.0f / sm_l[row];
        float inv1 = 1.0f / sm_l[row + 8];
#pragma unroll
        for (int nt = 0; nt < 4; nt++) {
            int col = h * 64 + wn * 32 + nt * 8 + 2 * qcol;
            *(__half2*)(g_attn + ((size_t)(b * T_ + i0 + row)) * DM_ + col) =
                __floats2half2_rn(o[nt][0] * inv0, o[nt][1] * inv0);
            *(__half2*)(g_attn + ((size_t)(b * T_ + i0 + row + 8)) * DM_ + col) =
                __floats2half2_rn(o[nt][2] * inv1, o[nt][3] * inv1);
        }
    }
}

// ---------------- host launcher ---------------------------------------------
extern "C" void kernel_launch(void* const* d_in, const int* in_sizes, int n_in,
                              void* d_out, int out_size) {
    const float* inputs = (const float*)d_in[0];
    const float* memory = (const float*)d_in[1];
    const float* w_qkv  = (const float*)d_in[2];
    const float* w_pos  = (const float*)d_in[3];
    const float* w_out  = (const float*)d_in[4];
    const float* uvar   = (const float*)d_in[5];
    const float* vvar   = (const float*)d_in[6];
    const float* gamma  = (const float*)d_in[7];
    const float* beta   = (const float*)d_in[8];
    float* out = (float*)d_out;

    __half *xln, *qkv, *phi, *R, *attn, *wqkv, *wpos, *wout;
    cudaGetSymbolAddress((void**)&xln,  g_xln);
    cudaGetSymbolAddress((void**)&qkv,  g_qkv);
    cudaGetSymbolAddress((void**)&phi,  g_phi);
    cudaGetSymbolAddress((void**)&R,    g_R);
    cudaGetSymbolAddress((void**)&attn, g_attn);
    cudaGetSymbolAddress((void**)&wqkv, g_wqkv);
    cudaGetSymbolAddress((void**)&wpos, g_wpos);
    cudaGetSymbolAddress((void**)&wout, g_wout);

    cudaFuncSetAttribute(attn_mma,
                         cudaFuncAttributeMaxDynamicSharedMemorySize, ATT_SMEM);
    cudaFuncSetAttribute(gemm_mma<true>,
                         cudaFuncAttributeMaxDynamicSharedMemorySize, GEMM_SMEM);
    cudaFuncSetAttribute(gemm_mma<false>,
                         cudaFuncAttributeMaxDynamicSharedMemorySize, GEMM_SMEM);

    // order keeps ncu capture slot (#4) on the QKV GEMM
    // 1) LayerNorm + concat (fp16 out)
    ln_kernel<<<B_ * L_, 256>>>(inputs, memory, gamma, beta);
    // 2) positional features (fp16 out)
    phi_kernel<<<L_, 256>>>();
    // 3) w_qkv -> fp16
    round_h_kernel<<<(3 * DM_ * DM_ / 4 + 255) / 256, 256>>>(w_qkv, wqkv, 3 * DM_ * DM_ / 4);
    // 4) QKV = xln @ w_qkv^T   [4096 x 3072 x 1024]
    gemm_mma<true><<<dim3(3072 / 128, (B_ * L_) / 128), 256, GEMM_SMEM>>>(
        xln, wqkv, qkv, B_ * L_, 3 * DM_, DM_);
    // 5) w_pos -> fp16
    round_h_kernel<<<(DM_ * DM_ / 4 + 255) / 256, 256>>>(w_pos, wpos, DM_ * DM_ / 4);
    // 6) R = phi @ w_pos^T     [1024 x 1024 x 1024]
    gemm_mma<true><<<dim3(DM_ / 128, L_ / 128), 256, GEMM_SMEM>>>(
        phi, wpos, R, L_, DM_, DM_);
    // 7) fused relative attention (fp16 tensor-core)
    attn_mma<<<dim3(T_ / 64, B_ * H_), 256, ATT_SMEM>>>(uvar, vvar);
    // 8) w_out -> fp16
    round_h_kernel<<<(DM_ * DM_ / 4 + 255) / 256, 256>>>(w_out, wout, DM_ * DM_ / 4);
    // 9) out = attn @ w_out^T  [2048 x 1024 x 1024]  (fp32 out)
    gemm_mma<false><<<dim3(DM_ / 128, (B_ * T_) / 128), 256, GEMM_SMEM>>>(
        attn, wout, out, B_ * T_, DM_, DM_);
}

// round 17
// speedup vs baseline: 1.1462x; 1.0662x over previous
#include <cuda_runtime.h>
#include <cuda_fp16.h>
#include <math.h>
#include <stdint.h>

#define B_ 4
#define T_ 512
#define TAU_ 512
#define L_ 1024
#define DM_ 1024
#define H_ 16
#define D_ 64

// ---------------- scratch (device globals; no allocations allowed) ----------
__device__ __half g_xln[B_ * L_ * DM_];        //  8 MB  LN out (fp16)
__device__ __half g_qkv[B_ * L_ * 3 * DM_];    // 24 MB  [B,L,3072] fp16
__device__ __half g_phi[L_ * DM_];             //  2 MB
__device__ __half g_R[L_ * DM_];               //  2 MB
__device__ __half g_attn[B_ * T_ * DM_];       //  4 MB
__device__ __half g_wqkv[3 * DM_ * DM_];       //  6 MB  fp16 weights
__device__ __half g_wpos[DM_ * DM_];           //  2 MB
__device__ __half g_wout[DM_ * DM_];           //  2 MB

__device__ __forceinline__ uint32_t smem_u32(const void* p) {
    uint32_t a;
    asm("{ .reg .u64 t; cvta.to.shared.u64 t, %1; cvt.u32.u64 %0, t; }" : "=r"(a) : "l"(p));
    return a;
}
// fp16 mma, fp32 accum: m16n8k16
__device__ __forceinline__ void mma_f16(float& c0, float& c1, float& c2, float& c3,
                                        uint32_t a0, uint32_t a1, uint32_t a2, uint32_t a3,
                                        uint32_t b0, uint32_t b1) {
    asm volatile(
        "mma.sync.aligned.m16n8k16.row.col.f32.f16.f16.f32 "
        "{%0,%1,%2,%3},{%4,%5,%6,%7},{%8,%9},{%0,%1,%2,%3};"
        : "+f"(c0), "+f"(c1), "+f"(c2), "+f"(c3)
        : "r"(a0), "r"(a1), "r"(a2), "r"(a3), "r"(b0), "r"(b1));
}
__device__ __forceinline__ void cp16(uint32_t dst, const void* src) {
    asm volatile("cp.async.cg.shared.global [%0], [%1], 16;" :: "r"(dst), "l"(src));
}
__device__ __forceinline__ void cp_commit() {
    asm volatile("cp.async.commit_group;" ::: "memory");
}
__device__ __forceinline__ void cp_wait0() {
    asm volatile("cp.async.wait_group 0;" ::: "memory");
}
__device__ __forceinline__ void cp_wait1() {
    asm volatile("cp.async.wait_group 1;" ::: "memory");
}
__device__ __forceinline__ void cp_wait2() {
    asm volatile("cp.async.wait_group 2;" ::: "memory");
}

// ---------------- convert weights fp32 -> fp16 -------------------------------
__global__ __launch_bounds__(256) void round_h_kernel(const float* __restrict__ src,
                                                      __half* __restrict__ dst, int n4) {
    int i = blockIdx.x * blockDim.x + threadIdx.x;
    if (i < n4) {
        float4 v = ((const float4*)src)[i];
        ((__half2*)dst)[2 * i]     = __floats2half2_rn(v.x, v.y);
        ((__half2*)dst)[2 * i + 1] = __floats2half2_rn(v.z, v.w);
    }
}

// ---------------- LayerNorm over concat(memory, inputs), fp16 out ------------
__global__ __launch_bounds__(256) void ln_kernel(const float* __restrict__ inputs,
                          const float* __restrict__ memory,
                          const float* __restrict__ gamma,
                          const float* __restrict__ beta) {
    int row = blockIdx.x;
    int b = row >> 10, l = row & 1023;
    const float* src = (l < TAU_) ? memory + ((size_t)b * TAU_ + l) * DM_
                                  : inputs + ((size_t)b * T_ + (l - TAU_)) * DM_;
    int tid = threadIdx.x;
    float4 x = ((const float4*)src)[tid];
    float s  = x.x + x.y + x.z + x.w;
    float ss = x.x * x.x + x.y * x.y + x.z * x.z + x.w * x.w;
#pragma unroll
    for (int off = 16; off; off >>= 1) {
        s  += __shfl_xor_sync(0xffffffffu, s, off);
        ss += __shfl_xor_sync(0xffffffffu, ss, off);
    }
    __shared__ float red[16];
    int wid = tid >> 5, lane = tid & 31;
    if (lane == 0) { red[wid] = s; red[8 + wid] = ss; }
    __syncthreads();
    float ts = 0.f, tss = 0.f;
#pragma unroll
    for (int i = 0; i < 8; i++) { ts += red[i]; tss += red[8 + i]; }
    float mu   = ts * (1.0f / DM_);
    float var  = tss * (1.0f / DM_) - mu * mu;
    float rstd = rsqrtf(var + 1e-5f);
    float4 g  = ((const float4*)gamma)[tid];
    float4 bb = ((const float4*)beta)[tid];
    __half2* dst = (__half2*)(g_xln + (size_t)row * DM_);
    dst[2 * tid]     = __floats2half2_rn((x.x - mu) * rstd * g.x + bb.x,
                                         (x.y - mu) * rstd * g.y + bb.y);
    dst[2 * tid + 1] = __floats2half2_rn((x.z - mu) * rstd * g.z + bb.z,
                                         (x.w - mu) * rstd * g.w + bb.w);
}

// ---------------- positional features phi[l, :], fp16 out --------------------
__global__ __launch_bounds__(256) void phi_kernel() {
    int l = blockIdx.x;
    float pos = (float)(L_ - 1 - l);
    for (int f = threadIdx.x; f < 512; f += blockDim.x) {
        float ex  = (float)(2 * f) / 1024.0f;
        float inv = powf(10000.0f, -ex);
        float a = pos * inv;
        float sn, cs;
        sincosf(a, &sn, &cs);
        g_phi[(size_t)l * DM_ + f]       = __float2half_rn(sn);
        g_phi[(size_t)l * DM_ + 512 + f] = __float2half_rn(cs);
    }
}

// ---------------- cp.async 3-stage fp16 GEMM: C = A @ B^T (R16 best) ---------
#define GST 36
#define STAGE_WORDS (128 * GST)
#define STAGE_BYTES (STAGE_WORDS * 4)
#define STAGES 3
#define GEMM_SMEM (STAGES * 2 * STAGE_WORDS * 4)   // 110592 B -> 2 CTAs/SM

#define GEMM_ISSUE(kcc, st) do {                                            \
    const __half* Ag = A  + (size_t)bm * K + (kcc) * 64;                    \
    const __half* Bg = Bm + (size_t)bn * K + (kcc) * 64;                    \
    uint32_t baseA = aAddr + (st) * STAGE_BYTES;                            \
    uint32_t baseB = bAddr + (st) * STAGE_BYTES;                            \
    _Pragma("unroll")                                                       \
    for (int p = 0; p < 4; p++) {                                           \
        int sgm = tid + 256 * p;                                            \
        int row = sgm >> 3, cs = sgm & 7;                                   \
        uint32_t off = (uint32_t)(row * GST + cs * 4) * 4;                  \
        cp16(baseA + off, Ag + (size_t)row * K + cs * 8);                   \
        cp16(baseB + off, Bg + (size_t)row * K + cs * 8);                   \
    }                                                                       \
} while (0)

template <bool HOUT>
__global__ __launch_bounds__(256, 2) void gemm_mma(const __half* __restrict__ A,
                                                   const __half* __restrict__ Bm,
                                                   void* __restrict__ Cv,
                                                   int M, int N, int K) {
    extern __shared__ uint32_t smem_u[];
    uint32_t* sA = smem_u;
    uint32_t* sB = smem_u + STAGES * STAGE_WORDS;
    uint32_t aAddr = smem_u32(sA);
    uint32_t bAddr = smem_u32(sB);

    int tid = threadIdx.x;
    int wid = tid >> 5, lane = tid & 31;
    int warp_m = wid >> 2, warp_n = wid & 3;    // 2m x 4n
    int bm = blockIdx.y * 128, bn = blockIdx.x * 128;
    int qrow = lane >> 2, qcol = lane & 3;

    float c[4][4][4];
#pragma unroll
    for (int mt = 0; mt < 4; mt++)
#pragma unroll
        for (int nt = 0; nt < 4; nt++)
#pragma unroll
            for (int e = 0; e < 4; e++) c[mt][nt][e] = 0.f;

    const int NC = K / 64;

    GEMM_ISSUE(0, 0); cp_commit();
    GEMM_ISSUE(1, 1); cp_commit();

    int st = 0;
    for (int kc = 0; kc < NC; kc++) {
        cp_wait1();
        __syncthreads();
        const uint32_t* cA = sA + st * STAGE_WORDS;
        const uint32_t* cB = sB + st * STAGE_WORDS;
#pragma unroll
        for (int ks = 0; ks < 4; ks++) {
            int kk = ks * 8;
            uint32_t af[4][4], bf[4][2];
#pragma unroll
            for (int mt = 0; mt < 4; mt++) {
                int r = warp_m * 64 + mt * 16 + qrow;
                af[mt][0] = cA[r * GST + kk + qcol];
                af[mt][1] = cA[(r + 8) * GST + kk + qcol];
                af[mt][2] = cA[r * GST + kk + qcol + 4];
                af[mt][3] = cA[(r + 8) * GST + kk + qcol + 4];
            }
#pragma unroll
            for (int nt = 0; nt < 4; nt++) {
                int rn = warp_n * 32 + nt * 8 + qrow;
                bf[nt][0] = cB[rn * GST + kk + qcol];
                bf[nt][1] = cB[rn * GST + kk + qcol + 4];
            }
#pragma unroll
            for (int mt = 0; mt < 4; mt++)
#pragma unroll
                for (int nt = 0; nt < 4; nt++)
                    mma_f16(c[mt][nt][0], c[mt][nt][1], c[mt][nt][2], c[mt][nt][3],
                            af[mt][0], af[mt][1], af[mt][2], af[mt][3],
                            bf[nt][0], bf[nt][1]);
        }
        int kn = kc + 2;
        if (kn < NC) {
            int sn = st + 2; if (sn >= STAGES) sn -= STAGES;
            GEMM_ISSUE(kn, sn);
        }
        cp_commit();
        __syncthreads();
        if (++st == STAGES) st = 0;
    }

#pragma unroll
    for (int mt = 0; mt < 4; mt++) {
        int row = bm + warp_m * 64 + mt * 16 + qrow;
#pragma unroll
        for (int nt = 0; nt < 4; nt++) {
            int col = bn + warp_n * 32 + nt * 8 + 2 * qcol;
            if (HOUT) {
                __half* Ch = (__half*)Cv;
                *(__half2*)(Ch + (size_t)row * N + col) =
                    __floats2half2_rn(c[mt][nt][0], c[mt][nt][1]);
                *(__half2*)(Ch + (size_t)(row + 8) * N + col) =
                    __floats2half2_rn(c[mt][nt][2], c[mt][nt][3]);
            } else {
                float* Cf = (float*)Cv;
                *(float2*)(Cf + (size_t)row * N + col) = make_float2(c[mt][nt][0], c[mt][nt][1]);
                *(float2*)(Cf + (size_t)(row + 8) * N + col) = make_float2(c[mt][nt][2], c[mt][nt][3]);
            }
        }
    }
}

// ---------------- cp.async-pipelined fp16 relative flash attention -----------
// Buffers: hR (R batch), hK (K tile, then transposed V), hVr (raw V), hP.
// V(jt) issued at tile start; R(jt+1) after phase A; K(jt+1) after phase D.
// Group invariant at tile entry: pending = {R(jt), K(jt)}.
#define AWW 36      // word stride of fp16 tiles (64 halves + pad)
#define AWH 72      // half stride (144 B, 16B-aligned)
#define ASW 68      // fp32 score row stride
#define AEW 132     // fp32 E ring stride
#define ATT_SMEM ((6 * 64 * AWW + 64 * ASW + 64 * AEW + 192) * 4)   // 107264 B

__global__ __launch_bounds__(256, 2) void attn_mma(const float* __restrict__ uvar,
                                                   const float* __restrict__ vvar) {
    extern __shared__ float sm[];
    __half* hQU = (__half*)sm;                         // [64][AWH]
    __half* hQV = hQU + 64 * AWH;                      // [64][AWH]
    __half* hR  = hQV + 64 * AWH;                      // [64][AWH] R batch
    __half* hK  = hR  + 64 * AWH;                      // [64][AWH] K, then V(d-major)
    __half* hVr = hK  + 64 * AWH;                      // [64][AWH] raw V (j-major)
    __half* hP  = hVr + 64 * AWH;                      // [64][AWH] probs
    float* sS   = (float*)(hP + 64 * AWH);             // [64][ASW] scores
    float* sE   = sS + 64 * ASW;                       // [64][AEW] E ring
    float* sm_m = sE + 64 * AEW;
    float* sm_l = sm_m + 64;
    float* sm_c = sm_l + 64;

    const uint32_t* uQU = (const uint32_t*)hQU;
    const uint32_t* uQV = (const uint32_t*)hQV;
    const uint32_t* uR  = (const uint32_t*)hR;
    const uint32_t* uK  = (const uint32_t*)hK;
    const uint32_t* uP  = (const uint32_t*)hP;

    int i0 = blockIdx.x * 64;
    int b  = blockIdx.y >> 4;
    int h  = blockIdx.y & 15;
    int tid = threadIdx.x;
    int wid = tid >> 5, lane = tid & 31;
    int wm = wid >> 1, wn = wid & 1;
    int qrow = lane >> 2, qcol = lane & 3;

    uint32_t adR  = smem_u32(hR);
    uint32_t adK  = smem_u32(hK);
    uint32_t adVr = smem_u32(hVr);

    // cp.async issue macros (2x 16B per thread each; every thread participates)
#define ISSUE_R(rbatch) do {                                                   \
    _Pragma("unroll")                                                          \
    for (int p = 0; p < 2; p++) {                                              \
        int s_ = tid + 256 * p; int r_ = s_ >> 3, sg_ = s_ & 7;                \
        int rr_ = (rbatch) + r_; rr_ = rr_ > (L_ - 1) ? (L_ - 1) : rr_;        \
        cp16(adR + (uint32_t)(r_ * AWH + sg_ * 8) * 2,                         \
             g_R + (size_t)rr_ * DM_ + h * 64 + sg_ * 8);                      \
    }                                                                          \
    cp_commit();                                                               \
} while (0)

#define ISSUE_K(jj0) do {                                                      \
    _Pragma("unroll")                                                          \
    for (int p = 0; p < 2; p++) {                                              \
        int s_ = tid + 256 * p; int j_ = s_ >> 3, sg_ = s_ & 7;                \
        int row_ = (jj0) + j_; row_ = row_ > (L_ - 1) ? (L_ - 1) : row_;       \
        cp16(adK + (uint32_t)(j_ * AWH + sg_ * 8) * 2,                         \
             g_qkv + ((size_t)(b * L_ + row_)) * 3072 + 1024 + h * 64 + sg_ * 8);\
    }                                                                          \
    cp_commit();                                                               \
} while (0)

#define ISSUE_V(jj0) do {                                                      \
    _Pragma("unroll")                                                          \
    for (int p = 0; p < 2; p++) {                                              \
        int s_ = tid + 256 * p; int j_ = s_ >> 3, sg_ = s_ & 7;                \
        cp16(adVr + (uint32_t)(j_ * AWH + sg_ * 8) * 2,                        \
             g_qkv + ((size_t)(b * L_ + (jj0) + j_)) * 3072 + 2048 + h * 64 + sg_ * 8);\
    }                                                                          \
    cp_commit();                                                               \
} while (0)

    // E-phase mma from hR into sE half hf
#define MMA_E(hf) do {                                                         \
    float ce[4][4];                                                            \
    _Pragma("unroll")                                                          \
    for (int nt = 0; nt < 4; nt++)                                             \
        _Pragma("unroll")                                                      \
        for (int e = 0; e < 4; e++) ce[nt][e] = 0.f;                           \
    _Pragma("unroll")                                                          \
    for (int ks = 0; ks < 4; ks++) {                                           \
        int kk = ks * 8;                                                       \
        int r = wm * 16 + qrow;                                                \
        uint32_t a0 = uQV[r * AWW + kk + qcol];                                \
        uint32_t a1 = uQV[(r + 8) * AWW + kk + qcol];                          \
        uint32_t a2 = uQV[r * AWW + kk + qcol + 4];                            \
        uint32_t a3 = uQV[(r + 8) * AWW + kk + qcol + 4];                      \
        _Pragma("unroll")                                                      \
        for (int nt = 0; nt < 4; nt++) {                                       \
            int rn = wn * 32 + nt * 8 + qrow;                                  \
            uint32_t b0 = uR[rn * AWW + kk + qcol];                            \
            uint32_t b1 = uR[rn * AWW + kk + qcol + 4];                        \
            mma_f16(ce[nt][0], ce[nt][1], ce[nt][2], ce[nt][3],                \
                    a0, a1, a2, a3, b0, b1);                                   \
        }                                                                      \
    }                                                                          \
    int row = wm * 16 + qrow;                                                  \
    _Pragma("unroll")                                                          \
    for (int nt = 0; nt < 4; nt++) {                                           \
        int col = (hf) * 64 + wn * 32 + nt * 8 + 2 * qcol;                     \
        sE[row * AEW + col]     = ce[nt][0];                                   \
        sE[row * AEW + col + 1] = ce[nt][1];                                   \
        sE[(row + 8) * AEW + col]     = ce[nt][2];                             \
        sE[(row + 8) * AEW + col + 1] = ce[nt][3];                             \
    }                                                                          \
} while (0)

    // load q tiles (16B vectorized), add u/v in fp32, store fp16
#pragma unroll
    for (int p = 0; p < 2; p++) {
        int s = tid + 256 * p;            // 0..511
        int i = s >> 3, seg = s & 7;
        uint4 q4 = *(const uint4*)(g_qkv + ((size_t)(b * L_ + TAU_ + i0 + i)) * 3072 + h * 64 + seg * 8);
        const __half* qh = (const __half*)&q4;
        const float* up = uvar + h * 64 + seg * 8;
        const float* vp = vvar + h * 64 + seg * 8;
        __half2 ou[4], ov[4];
#pragma unroll
        for (int k = 0; k < 4; k++) {
            float q0 = __half2float(qh[2 * k]), q1 = __half2float(qh[2 * k + 1]);
            ou[k] = __floats2half2_rn(q0 + up[2 * k], q1 + up[2 * k + 1]);
            ov[k] = __floats2half2_rn(q0 + vp[2 * k], q1 + vp[2 * k + 1]);
        }
        *(uint4*)(hQU + i * AWH + seg * 8) = *(uint4*)ou;
        *(uint4*)(hQV + i * AWH + seg * 8) = *(uint4*)ov;
    }
    if (tid < 64) { sm_m[tid] = -INFINITY; sm_l[tid] = 0.f; }

    float o[4][4];
#pragma unroll
    for (int nt = 0; nt < 4; nt++)
#pragma unroll
        for (int e = 0; e < 4; e++) o[nt][e] = 0.f;

    int ntiles = (TAU_ + i0 + 63) / 64 + 1;

    // prologue: first R batch + E lower half; prefetch R(0), K(0)
    ISSUE_R(448 - i0);
    cp_wait0(); __syncthreads();          // R batch0 + Q tiles visible
    MMA_E(((448 - i0) >> 6) & 1);
    __syncthreads();                      // hR reads done
    ISSUE_R(512 - i0);                    // R(0)
    ISSUE_K(0);                           // K(0)

    for (int jt = 0; jt < ntiles; jt++) {
        int j0 = jt * 64;
        int rband = j0 + 448 - i0;

        // T0: issue V(jt); ensure R(jt) landed
        ISSUE_V(j0);
        cp_wait2(); __syncthreads();

        // ---- Phase A: E upper half from hR ----
        MMA_E(((rband + 64) >> 6) & 1);
        __syncthreads();                  // hR reads done
        ISSUE_R(j0 + 64 + 512 - i0);      // R(jt+1)
        cp_wait2(); __syncthreads();      // K(jt) landed

        // ---- Phase B: S = QU @ K^T ----
        {
            float cs[4][4];
#pragma unroll
            for (int nt = 0; nt < 4; nt++)
#pragma unroll
                for (int e = 0; e < 4; e++) cs[nt][e] = 0.f;
#pragma unroll
            for (int ks = 0; ks < 4; ks++) {
                int kk = ks * 8;
                int r = wm * 16 + qrow;
                uint32_t a0 = uQU[r * AWW + kk + qcol];
                uint32_t a1 = uQU[(r + 8) * AWW + kk + qcol];
                uint32_t a2 = uQU[r * AWW + kk + qcol + 4];
                uint32_t a3 = uQU[(r + 8) * AWW + kk + qcol + 4];
#pragma unroll
                for (int nt = 0; nt < 4; nt++) {
                    int rn = wn * 32 + nt * 8 + qrow;
                    uint32_t b0 = uK[rn * AWW + kk + qcol];
                    uint32_t b1 = uK[rn * AWW + kk + qcol + 4];
                    mma_f16(cs[nt][0], cs[nt][1], cs[nt][2], cs[nt][3],
                            a0, a1, a2, a3, b0, b1);
                }
            }
            int row = wm * 16 + qrow;
#pragma unroll
            for (int nt = 0; nt < 4; nt++) {
                int col = wn * 32 + nt * 8 + 2 * qcol;
                sS[row * ASW + col]     = cs[nt][0];
                sS[row * ASW + col + 1] = cs[nt][1];
                sS[(row + 8) * ASW + col]     = cs[nt][2];
                sS[(row + 8) * ASW + col + 1] = cs[nt][3];
            }
        }
        __syncthreads();                  // hK reads done (transpose will overwrite)
        cp_wait1(); __syncthreads();      // V(jt) landed in hVr

        // ---- Phase C: softmax (sS,sE -> hP) + transpose hVr -> hK ----
        {
            int row = tid >> 2, cbase = (tid & 3) * 16;
            int gi = i0 + row;
            float oldm = sm_m[row];
            int sb = rband + 63 - row;
            float s16[16], mx = -INFINITY;
#pragma unroll
            for (int x = 0; x < 16; x++) {
                int jp = cbase + x;
                float s = (sS[row * ASW + jp] + sE[row * AEW + ((sb + jp) & 127)]) * 0.125f;
                if (j0 + jp > TAU_ + gi) s = -1e30f;
                s16[x] = s;
                mx = fmaxf(mx, s);
            }
            mx = fmaxf(mx, __shfl_xor_sync(0xffffffffu, mx, 1));
            mx = fmaxf(mx, __shfl_xor_sync(0xffffffffu, mx, 2));
            float mnew = fmaxf(oldm, mx);
            float corr = __expf(oldm - mnew);
            float ps = 0.f;
#pragma unroll
            for (int x = 0; x < 16; x += 2) {
                float p0 = __expf(s16[x] - mnew);
                float p1 = __expf(s16[x + 1] - mnew);
                *(__half2*)(hP + row * AWH + cbase + x) = __floats2half2_rn(p0, p1);
                ps += p0 + p1;
            }
            ps += __shfl_xor_sync(0xffffffffu, ps, 1);
            ps += __shfl_xor_sync(0xffffffffu, ps, 2);
            if ((tid & 3) == 0) {
                sm_m[row] = mnew;
                sm_l[row] = sm_l[row] * corr + ps;
                sm_c[row] = corr;
            }
        }
        // transpose hVr (j-major) -> hK (d-major), smem-to-smem
#pragma unroll
        for (int p = 0; p < 2; p++) {
            int s = tid + 256 * p;
            int j = s & 63, dg = s >> 6;   // consecutive lanes -> consecutive j
            uint4 v4 = *(const uint4*)(hVr + j * AWH + dg * 8);
            const __half* vh = (const __half*)&v4;
#pragma unroll
            for (int k = 0; k < 8; k++)
                hK[(dg * 8 + k) * AWH + j] = vh[k];
        }
        __syncthreads();

        // ---- Phase D: O = O*corr + P @ V ----
        {
            float cr0 = sm_c[wm * 16 + qrow];
            float cr1 = sm_c[wm * 16 + qrow + 8];
#pragma unroll
            for (int nt = 0; nt < 4; nt++) {
                o[nt][0] *= cr0; o[nt][1] *= cr0;
                o[nt][2] *= cr1; o[nt][3] *= cr1;
            }
#pragma unroll
            for (int ks = 0; ks < 4; ks++) {
                int kk = ks * 8;
                int r = wm * 16 + qrow;
                uint32_t a0 = uP[r * AWW + kk + qcol];
                uint32_t a1 = uP[(r + 8) * AWW + kk + qcol];
                uint32_t a2 = uP[r * AWW + kk + qcol + 4];
                uint32_t a3 = uP[(r + 8) * AWW + kk + qcol + 4];
#pragma unroll
                for (int nt = 0; nt < 4; nt++) {
                    int rn = wn * 32 + nt * 8 + qrow;
                    uint32_t b0 = uK[rn * AWW + kk + qcol];
                    uint32_t b1 = uK[rn * AWW + kk + qcol + 4];
                    mma_f16(o[nt][0], o[nt][1], o[nt][2], o[nt][3],
                            a0, a1, a2, a3, b0, b1);
                }
            }
        }
        __syncthreads();                  // hK (V) reads done before K prefetch
        ISSUE_K(j0 + 64);                 // K(jt+1), row-clamped
    }

    cp_wait0();                           // drain trailing prefetches

    // write O fp16 (consumed by out-proj GEMM)
    {
        int row = wm * 16 + qrow;
        float inv0 = 1.0f / sm_l[row];
        float inv1 = 1.0f / sm_l[row + 8];
#pragma unroll
        for (int nt = 0; nt < 4; nt++) {
            int col = h * 64 + wn * 32 + nt * 8 + 2 * qcol;
            *(__half2*)(g_attn + ((size_t)(b * T_ + i0 + row)) * DM_ + col) =
                __floats2half2_rn(o[nt][0] * inv0, o[nt][1] * inv0);
            *(__half2*)(g_attn + ((size_t)(b * T_ + i0 + row + 8)) * DM_ + col) =
                __floats2half2_rn(o[nt][2] * inv1, o[nt][3] * inv1);
        }
    }
#undef ISSUE_R
#undef ISSUE_K
#undef ISSUE_V
#undef MMA_E
}

// ---------------- host launcher ---------------------------------------------
extern "C" void kernel_launch(void* const* d_in, const int* in_sizes, int n_in,
                              void* d_out, int out_size) {
    const float* inputs = (const float*)d_in[0];
    const float* memory = (const float*)d_in[1];
    const float* w_qkv  = (const float*)d_in[2];
    const float* w_pos  = (const float*)d_in[3];
    const float* w_out  = (const float*)d_in[4];
    const float* uvar   = (const float*)d_in[5];
    const float* vvar   = (const float*)d_in[6];
    const float* gamma  = (const float*)d_in[7];
    const float* beta   = (const float*)d_in[8];
    float* out = (float*)d_out;

    __half *xln, *qkv, *phi, *R, *attn, *wqkv, *wpos, *wout;
    cudaGetSymbolAddress((void**)&xln,  g_xln);
    cudaGetSymbolAddress((void**)&qkv,  g_qkv);
    cudaGetSymbolAddress((void**)&phi,  g_phi);
    cudaGetSymbolAddress((void**)&R,    g_R);
    cudaGetSymbolAddress((void**)&attn, g_attn);
    cudaGetSymbolAddress((void**)&wqkv, g_wqkv);
    cudaGetSymbolAddress((void**)&wpos, g_wpos);
    cudaGetSymbolAddress((void**)&wout, g_wout);

    cudaFuncSetAttribute(attn_mma,
                         cudaFuncAttributeMaxDynamicSharedMemorySize, ATT_SMEM);
    cudaFuncSetAttribute(gemm_mma<true>,
                         cudaFuncAttributeMaxDynamicSharedMemorySize, GEMM_SMEM);
    cudaFuncSetAttribute(gemm_mma<false>,
                         cudaFuncAttributeMaxDynamicSharedMemorySize, GEMM_SMEM);

    // order keeps ncu capture slot (#4) on the QKV GEMM
    // 1) LayerNorm + concat (fp16 out)
    ln_kernel<<<B_ * L_, 256>>>(inputs, memory, gamma, beta);
    // 2) positional features (fp16 out)
    phi_kernel<<<L_, 256>>>();
    // 3) w_qkv -> fp16
    round_h_kernel<<<(3 * DM_ * DM_ / 4 + 255) / 256, 256>>>(w_qkv, wqkv, 3 * DM_ * DM_ / 4);
    // 4) QKV = xln @ w_qkv^T   [4096 x 3072 x 1024]
    gemm_mma<true><<<dim3(3072 / 128, (B_ * L_) / 128), 256, GEMM_SMEM>>>(
        xln, wqkv, qkv, B_ * L_, 3 * DM_, DM_);
    // 5) w_pos -> fp16
    round_h_kernel<<<(DM_ * DM_ / 4 + 255) / 256, 256>>>(w_pos, wpos, DM_ * DM_ / 4);
    // 6) R = phi @ w_pos^T     [1024 x 1024 x 1024]
    gemm_mma<true><<<dim3(DM_ / 128, L_ / 128), 256, GEMM_SMEM>>>(
        phi, wpos, R, L_, DM_, DM_);
    // 7) fused relative attention (fp16 tensor-core, cp.async pipelined)
    attn_mma<<<dim3(T_ / 64, B_ * H_), 256, ATT_SMEM>>>(uvar, vvar);
    // 8) w_out -> fp16
    round_h_kernel<<<(DM_ * DM_ / 4 + 255) / 256, 256>>>(w_out, wout, DM_ * DM_ / 4);
    // 9) out = attn @ w_out^T  [2048 x 1024 x 1024]  (fp32 out)
    gemm_mma<false><<<dim3(DM_ / 128, (B_ * T_) / 128), 256, GEMM_SMEM>>>(
        attn, wout, out, B_ * T_, DM_, DM_);
}